// round 1
// baseline (speedup 1.0000x reference)
#include <cuda_runtime.h>

#define BIGV 10000000000.0f
#define L2E  1.4426950408889634f
#define LN2  0.6931471805599453f

__device__ __forceinline__ float ex2f_(float x){ float r; asm("ex2.approx.f32 %0, %1;" : "=f"(r) : "f"(x)); return r; }
__device__ __forceinline__ float lg2f_(float x){ float r; asm("lg2.approx.f32 %0, %1;" : "=f"(r) : "f"(x)); return r; }

// One warp processes TWO pairs (a,b0) and (a,b0+1) in anti-phase:
//   pair A runs diagonals 0..254, pair B runs diagonals 0..254 offset by +128 steps.
//   At step p, row i works on "virtual diagonal" ja = p - i; phase = A if ja<128 else B,
//   j = ja & 127. Steady state is fully dense (all 128 rows busy).
// Thread `lane` owns rows 4*lane .. 4*lane+3. One shuffle per step carries the
// warp-boundary prev1; prev2-across-boundary is last step's shuffle value.
__global__ __launch_bounds__(128)
void sdtw_kernel(const float* __restrict__ X, const float* __restrict__ Y,
                 float* __restrict__ out)
{
    // two Y tiles, each: 1024 floats swizzled y + 128 floats sqy = 1152 floats
    __shared__ float sy[2 * 1152];

    const int tid  = threadIdx.x;
    const int lane = tid & 31;
    const int wid  = tid >> 5;

    const int bgrp = blockIdx.x & 7;    // 0..7  -> b0 = 2*bgrp
    const int agrp = blockIdx.x >> 3;   // 0..31
    const int b0   = bgrp * 2;
    const int a    = agrp * 4 + wid;

    // ---- load Y tiles (b0, b0+1) into smem, transposed+regioned ----
    // layout: sy[tile*1152 + (j&3)*256 + k*32 + (j>>2)] = Y[b0+tile][j][k]
    //         sy[tile*1152 + 1024 + (j&3)*32 + (j>>2)]  = |Y[b0+tile][j]|^2
    for (int rep = 0; rep < 2; ++rep) {
        int gr   = tid + rep * 128;          // 0..255
        int tile = gr >> 7;
        int j    = gr & 127;
        const float* yrow = Y + (size_t)(b0 + tile) * (128 * 8) + j * 8;
        float sq = 0.f;
        int base = tile * 1152 + (j & 3) * 256 + (j >> 2);
        #pragma unroll
        for (int k = 0; k < 8; ++k) {
            float vv = yrow[k];
            sq = fmaf(vv, vv, sq);
            sy[base + k * 32] = vv;
        }
        sy[tile * 1152 + 1024 + (j & 3) * 32 + (j >> 2)] = sq;
    }

    // ---- load this thread's 4 X rows into registers ----
    float x[4][8], sqx[4];
    {
        const float* xp = X + (size_t)a * (128 * 8) + lane * 32;
        #pragma unroll
        for (int s = 0; s < 4; ++s) {
            float acc = 0.f;
            #pragma unroll
            for (int k = 0; k < 8; ++k) {
                x[s][k] = xp[s * 8 + k];
                acc = fmaf(x[s][k], x[s][k], acc);
            }
            sqx[s] = acc;
        }
    }
    __syncthreads();

    // DP state: v[p&1][s] holds the value written at step with that parity.
    // At step p: write -> v[p&1], prev1 -> v[(p+1)&1], prev2 -> v[p&1] (read before write,
    // guaranteed by reverse slot order).
    float v[2][4];
    #pragma unroll
    for (int s = 0; s < 4; ++s) { v[0][s] = BIGV; v[1][s] = BIGV; }

    // Y register pipeline: yp[(p)&3] loaded at step p; slot s at step p uses yp[(p-s)&3].
    float yp[4][8], yq[4];
    #pragma unroll
    for (int q = 0; q < 4; ++q) {
        yq[q] = 0.f;
        #pragma unroll
        for (int k = 0; k < 8; ++k) yp[q][k] = 0.f;
    }

    float shPrev = BIGV;                 // lane-1 slot3 value from step p-2
    const int lane4 = lane * 4;
    const int outA  = a * 16 + b0;

    for (int p0 = 0; p0 < 384; p0 += 4) {
        #pragma unroll
        for (int u = 0; u < 4; ++u) {
            const int p    = p0 + u;
            const int wIdx = u & 1;
            const int rIdx = wIdx ^ 1;
            const int ja0  = p - lane4;  // virtual diagonal for slot 0

            // load Y row for slot0 (buffer u): conflict-free scalar LDS
            {
                int jl   = ja0 < 0 ? 0 : (ja0 > 255 ? 255 : ja0);
                int tile = jl >> 7;
                int rr   = jl & 127;
                int base = tile * 1152 + (rr & 3) * 256 + (rr >> 2);
                #pragma unroll
                for (int k = 0; k < 8; ++k) yp[u][k] = sy[base + k * 32];
                yq[u] = sy[tile * 1152 + 1024 + (rr & 3) * 32 + (rr >> 2)];
            }

            // warp-boundary prev1 (row 4*lane-1 at step p-1)
            const float sh1 = __shfl_up_sync(0xffffffffu, v[rIdx][3], 1);

            // reverse slot order: slot s reads v[wIdx][s-1] (prev2) before slot s-1 overwrites it
            #pragma unroll
            for (int s = 3; s >= 0; --s) {
                const int  ja    = ja0 - s;
                const bool valid = ((unsigned)ja) < 256u;
                const bool pj0   = (ja & 127) == 0;   // logical j == 0 (both phases)

                float left = pj0 ? BIGV : v[rIdx][s];
                float upv, diag;
                if (s == 0) {
                    upv = (lane == 0) ? BIGV : sh1;
                    if (lane == 0) diag = pj0 ? 0.0f : BIGV;      // corner at (0,0) of A (p=0) and B (p=128)
                    else           diag = pj0 ? BIGV : shPrev;
                } else {
                    upv  = v[rIdx][s - 1];
                    diag = pj0 ? BIGV : v[wIdx][s - 1];
                }

                // softmin(upv, left, diag), gamma = 1
                float m = fminf(fminf(upv, left), diag);
                float e = ex2f_((m - upv)  * L2E)
                        + ex2f_((m - left) * L2E)
                        + ex2f_((m - diag) * L2E);
                float sm = fmaf(-LN2, lg2f_(e), m);

                // squared distance d = |x|^2 + |y|^2 - 2 x.y
                const float* yb = yp[(u - s) & 3];
                float dot = 0.f;
                #pragma unroll
                for (int k = 0; k < 8; ++k) dot = fmaf(x[s][k], yb[k], dot);
                float d = fmaf(-2.0f, dot, sqx[s] + yq[(u - s) & 3]);

                v[wIdx][s] = valid ? (d + sm) : BIGV;
            }

            // harvest: A result at p=254 (row 127, j=127), B result at p=382
            if (p == 254 && lane == 31) out[outA]     = v[wIdx][3];
            if (p == 382 && lane == 31) out[outA + 1] = v[wIdx][3];

            shPrev = sh1;
        }
    }
}

extern "C" void kernel_launch(void* const* d_in, const int* in_sizes, int n_in,
                              void* d_out, int out_size)
{
    const float* X = (const float*)d_in[0];
    const float* Y = (const float*)d_in[1];
    // safety: X is the larger tensor (128*128*8 vs 16*128*8)
    if (n_in >= 2 && in_sizes[0] < in_sizes[1]) {
        const float* t = X; X = Y; Y = t;
    }
    float* out = (float*)d_out;

    // 256 blocks x 128 threads: block = (4 a-values) x (one b-pair), warp = 2 fused pairs
    sdtw_kernel<<<256, 128>>>(X, Y, out);
}

// round 2
// speedup vs baseline: 1.0106x; 1.0106x over previous
#include <cuda_runtime.h>

#define BIGV 10000000000.0f
#define L2E  1.4426950408889634f
#define LN2  0.6931471805599453f

__device__ __forceinline__ float ex2f_(float x){ float r; asm("ex2.approx.f32 %0, %1;" : "=f"(r) : "f"(x)); return r; }
__device__ __forceinline__ float lg2f_(float x){ float r; asm("lg2.approx.f32 %0, %1;" : "=f"(r) : "f"(x)); return r; }

// One warp = two (a,b) pairs fused in anti-phase (128-step offset), 4 rows/thread,
// wavefront over anti-diagonals, DP held in registers in log2-scaled domain.
__global__ __launch_bounds__(128)
void sdtw_kernel(const float* __restrict__ X, const float* __restrict__ Y,
                 float* __restrict__ out)
{
    // two Y tiles: swizzled y rows (1024 f) + pre-scaled sqy (128 f) each
    // sy[tile*1152 + (j&3)*256 + k*32 + (j>>2)] = Y[b0+tile][j][k]
    // sy[tile*1152 + 1024 + (j&3)*32 + (j>>2)] = L2E*|Y[b0+tile][j]|^2
    __shared__ float sy[2 * 1152];

    const int tid  = threadIdx.x;
    const int lane = tid & 31;
    const int wid  = tid >> 5;

    const int b0 = (blockIdx.x & 7) * 2;
    const int a  = (blockIdx.x >> 3) * 4 + wid;

    for (int rep = 0; rep < 2; ++rep) {
        int gr   = tid + rep * 128;
        int tile = gr >> 7;
        int j    = gr & 127;
        const float* yrow = Y + (size_t)(b0 + tile) * 1024 + j * 8;
        float sq = 0.f;
        int base = tile * 1152 + (j & 3) * 256 + (j >> 2);
        #pragma unroll
        for (int k = 0; k < 8; ++k) {
            float vv = yrow[k];
            sq = fmaf(vv, vv, sq);
            sy[base + k * 32] = vv;
        }
        sy[tile * 1152 + 1024 + (j & 3) * 32 + (j >> 2)] = sq * L2E;
    }

    // X rows pre-scaled: xs = -2*L2E*x, sqx' = L2E*|x|^2  -> d' = L2E*d directly
    float xs[4][8], sqx[4];
    {
        const float* xp = X + (size_t)a * 1024 + lane * 32;
        #pragma unroll
        for (int s = 0; s < 4; ++s) {
            float acc = 0.f;
            #pragma unroll
            for (int k = 0; k < 8; ++k) {
                float vv = xp[s * 8 + k];
                acc = fmaf(vv, vv, acc);
                xs[s][k] = vv * (-2.0f * L2E);
            }
            sqx[s] = acc * L2E;
        }
    }
    __syncthreads();

    float v[2][4];
    #pragma unroll
    for (int s = 0; s < 4; ++s) { v[0][s] = BIGV; v[1][s] = BIGV; }

    float yp[4][8], yq[4];
    #pragma unroll
    for (int q = 0; q < 4; ++q) {
        yq[q] = 0.f;
        #pragma unroll
        for (int k = 0; k < 8; ++k) yp[q][k] = 0.f;
    }

    float shPrev = BIGV;
    const int lane4 = lane * 4;
    const int outA  = a * 16 + b0;

    for (int p0 = 0; p0 < 384; p0 += 4) {
        // j0 is a multiple of 4 -> within this block (j&3)==u, (j>>2) constant.
        const int j0       = p0 - lane4;
        const unsigned jb  = (unsigned)j0 & 255u;   // wrap keeps smem in-bounds; wrapped rows feed only invalid cells
        const int ybase    = (int)((jb >> 7) * 1152u + ((jb >> 2) & 31u));
        const bool bj0     = ((jb & 127u) == 0u);   // j==0 boundary possible only at cell s==u

        // validity per constant c = u - s in [-3,3]
        bool vd[7];
        #pragma unroll
        for (int c = 0; c < 7; ++c) vd[c] = ((unsigned)(j0 + c - 3) < 256u);

        #pragma unroll
        for (int u = 0; u < 4; ++u) {
            const int wIdx = u & 1;
            const int rIdx = wIdx ^ 1;

            // Y row for slot0 of this step: immediate-offset, conflict-free LDS
            #pragma unroll
            for (int k = 0; k < 8; ++k) yp[u][k] = sy[ybase + u * 256 + k * 32];
            yq[u] = sy[ybase + 1024 + u * 32];

            const float sh1 = __shfl_up_sync(0xffffffffu, v[rIdx][3], 1);

            // reverse slot order: slot s reads v[wIdx][s-1] (prev2) before slot s-1 writes it
            #pragma unroll
            for (int s = 3; s >= 0; --s) {
                float upv, left, diag;
                if (s == 0) {
                    upv = (lane == 0) ? BIGV : sh1;
                    if (u == 0) {
                        left = bj0 ? BIGV : v[rIdx][0];
                        if (lane == 0) diag = bj0 ? 0.0f : BIGV;   // corner of each phase
                        else           diag = bj0 ? BIGV : shPrev;
                    } else {
                        left = v[rIdx][0];
                        diag = (lane == 0) ? BIGV : shPrev;
                    }
                } else {
                    upv = v[rIdx][s - 1];
                    if (s == u) {
                        left = bj0 ? BIGV : v[rIdx][s];
                        diag = bj0 ? BIGV : v[wIdx][s - 1];
                    } else {
                        left = v[rIdx][s];
                        diag = v[wIdx][s - 1];
                    }
                }

                // softmin in log2 domain (gamma=1): values pre-scaled by L2E
                float m  = fminf(fminf(upv, left), diag);
                float e  = ex2f_(m - upv) + ex2f_(m - left) + ex2f_(m - diag);
                float sm = m - lg2f_(e);

                // d' = L2E*(|x|^2+|y|^2-2 x.y): acc seeded with scaled norms
                const float* yb = yp[(u - s) & 3];
                float acc = sqx[s] + yq[(u - s) & 3];
                #pragma unroll
                for (int k = 0; k < 8; ++k) acc = fmaf(xs[s][k], yb[k], acc);

                v[wIdx][s] = vd[u - s + 3] ? (acc + sm) : BIGV;
            }

            // harvest: pair A at p=254 (p0=252,u=2), pair B at p=382 (p0=380,u=2)
            if (u == 2 && lane == 31) {
                if (p0 == 252) out[outA]     = v[0][3] * LN2;
                if (p0 == 380) out[outA + 1] = v[0][3] * LN2;
            }

            shPrev = sh1;
        }
    }
}

extern "C" void kernel_launch(void* const* d_in, const int* in_sizes, int n_in,
                              void* d_out, int out_size)
{
    const float* X = (const float*)d_in[0];
    const float* Y = (const float*)d_in[1];
    if (n_in >= 2 && in_sizes[0] < in_sizes[1]) {
        const float* t = X; X = Y; Y = t;
    }
    float* out = (float*)d_out;

    sdtw_kernel<<<256, 128>>>(X, Y, out);
}

// round 3
// speedup vs baseline: 1.0722x; 1.0609x over previous
#include <cuda_runtime.h>

#define BIGV 10000000000.0f
#define L2E  1.4426950408889634f
#define LN2  0.6931471805599453f

typedef unsigned long long u64;

__device__ __forceinline__ float ex2f_(float x){ float r; asm("ex2.approx.f32 %0, %1;" : "=f"(r) : "f"(x)); return r; }
__device__ __forceinline__ float lg2f_(float x){ float r; asm("lg2.approx.f32 %0, %1;" : "=f"(r) : "f"(x)); return r; }
__device__ __forceinline__ u64 pk2(float lo, float hi){ u64 r; asm("mov.b64 %0,{%1,%2};" : "=l"(r) : "f"(lo), "f"(hi)); return r; }
__device__ __forceinline__ void upk2(float& lo, float& hi, u64 v){ asm("mov.b64 {%0,%1},%2;" : "=f"(lo), "=f"(hi) : "l"(v)); }
__device__ __forceinline__ u64 fma2(u64 a, u64 b, u64 c){ u64 r; asm("fma.rn.f32x2 %0,%1,%2,%3;" : "=l"(r) : "l"(a), "l"(b), "l"(c)); return r; }

// One warp = two (a,b) pairs fused in anti-phase (128-step offset), 4 rows/thread.
// DP value carried in exp-split form V = g - lg2(e), e in [1,2):
//   no lg2 in the loop; softmin shift = min over g (any shift is mathematically exact).
__global__ __launch_bounds__(128)
void sdtw_kernel(const float* __restrict__ X, const float* __restrict__ Y,
                 float* __restrict__ out)
{
    // per tile: y rows as k-pairs  sy[t*1152 + (j&3)*256 + (k>>1)*64 + (j>>2)*2 + (k&1)]
    //           sqy (L2E-scaled)   sy[t*1152 + 1024 + (j&3)*32 + (j>>2)]
    __shared__ __align__(8) float sy[2 * 1152];

    const int tid  = threadIdx.x;
    const int lane = tid & 31;
    const int wid  = tid >> 5;

    const int b0 = (blockIdx.x & 7) * 2;
    const int a  = (blockIdx.x >> 3) * 4 + wid;

    for (int rep = 0; rep < 2; ++rep) {
        int gr   = tid + rep * 128;
        int tile = gr >> 7;
        int j    = gr & 127;
        const float* yrow = Y + (size_t)(b0 + tile) * 1024 + j * 8;
        float sq = 0.f;
        int base = tile * 1152 + (j & 3) * 256 + (j >> 2) * 2;
        #pragma unroll
        for (int k = 0; k < 8; ++k) {
            float vv = yrow[k];
            sq = fmaf(vv, vv, sq);
            sy[base + (k >> 1) * 64 + (k & 1)] = vv;
        }
        sy[tile * 1152 + 1024 + (j & 3) * 32 + (j >> 2)] = sq * L2E;
    }

    // X rows: packed xs2 = -2*L2E*x (k-pairs), sqx = L2E*|x|^2
    u64   xs2[4][4];
    float sqx[4];
    {
        const float* xp = X + (size_t)a * 1024 + lane * 32;
        #pragma unroll
        for (int s = 0; s < 4; ++s) {
            float acc = 0.f;
            #pragma unroll
            for (int kp = 0; kp < 4; ++kp) {
                float f0 = xp[s * 8 + 2 * kp];
                float f1 = xp[s * 8 + 2 * kp + 1];
                acc = fmaf(f0, f0, fmaf(f1, f1, acc));
                xs2[s][kp] = pk2(f0 * (-2.0f * L2E), f1 * (-2.0f * L2E));
            }
            sqx[s] = acc * L2E;
        }
    }
    __syncthreads();

    // DP state (double-buffered by step parity), exp-split channels
    float g[2][4], e[2][4];
    #pragma unroll
    for (int s = 0; s < 4; ++s) {
        g[0][s] = BIGV; g[1][s] = BIGV;
        e[0][s] = 1.0f; e[1][s] = 1.0f;
    }

    // Y register pipeline: buffer (p&3) loaded at step p; slot s uses (p-s)&3
    u64   yp2[4][4];
    float yq[4];
    #pragma unroll
    for (int q = 0; q < 4; ++q) {
        yq[q] = 0.f;
        #pragma unroll
        for (int kp = 0; kp < 4; ++kp) yp2[q][kp] = 0ull;
    }

    float shPg = BIGV, shPe = 1.0f;   // lane-boundary diag (from step p-2)
    const int lane4 = lane * 4;
    const int outA  = a * 16 + b0;

    for (int p0 = 0; p0 < 384; p0 += 4) {
        // j0 multiple of 4 -> (j&3)==u within block, (j>>2) constant
        const int j0      = p0 - lane4;
        const unsigned jb = (unsigned)j0 & 255u;
        const int tOff    = (int)((jb >> 7) * 1152u);
        const int ybase   = tOff + (int)((jb >> 2) & 31u) * 2;
        const int qbase   = tOff + 1024 + (int)((jb >> 2) & 31u);
        const bool bj0    = ((jb & 127u) == 0u);

        bool vd[7];
        #pragma unroll
        for (int c = 0; c < 7; ++c) vd[c] = ((unsigned)(j0 + c - 3) < 256u);

        #pragma unroll
        for (int u = 0; u < 4; ++u) {
            const int wIdx = u & 1;
            const int rIdx = wIdx ^ 1;

            // Y row for slot0 of this step: 4x LDS.64 + 1x LDS.32, immediate offsets
            #pragma unroll
            for (int kp = 0; kp < 4; ++kp)
                yp2[u][kp] = *reinterpret_cast<const u64*>(&sy[ybase + u * 256 + kp * 64]);
            yq[u] = sy[qbase + u * 32];

            const float sh1g = __shfl_up_sync(0xffffffffu, g[rIdx][3], 1);
            const float sh1e = __shfl_up_sync(0xffffffffu, e[rIdx][3], 1);

            // reverse slot order: slot s reads (g,e)[wIdx][s-1] (prev2) before slot s-1 writes
            #pragma unroll
            for (int s = 3; s >= 0; --s) {
                float gu, gl, gd, eu, el, ed;
                if (s == 0) {
                    gu = (lane == 0) ? BIGV : sh1g;  eu = sh1e;
                    if (u == 0) {
                        gl = bj0 ? BIGV : g[rIdx][0];  el = e[rIdx][0];
                        if (lane == 0) { gd = bj0 ? 0.0f : BIGV;  ed = 1.0f; }
                        else           { gd = bj0 ? BIGV : shPg;  ed = shPe; }
                    } else {
                        gl = g[rIdx][0];               el = e[rIdx][0];
                        gd = (lane == 0) ? BIGV : shPg; ed = shPe;
                    }
                } else {
                    gu = g[rIdx][s - 1];  eu = e[rIdx][s - 1];
                    if (s == u) {
                        gl = bj0 ? BIGV : g[rIdx][s];      el = e[rIdx][s];
                        gd = bj0 ? BIGV : g[wIdx][s - 1];  ed = e[wIdx][s - 1];
                    } else {
                        gl = g[rIdx][s];      el = e[rIdx][s];
                        gd = g[wIdx][s - 1];  ed = e[wIdx][s - 1];
                    }
                }

                // exp-split softmin: shift by m = min(g); one term is exactly e_i
                float m  = fminf(fminf(gu, gl), gd);
                float tu = ex2f_(m - gu);
                float tl = ex2f_(m - gl);
                float td = ex2f_(m - gd);
                float ss = fmaf(eu, tu, fmaf(el, tl, ed * td));   // ss in [1, 6)

                // exact renorm: e_new = ss * 2^-k in [1,2), k in {0,1,2}
                bool  c2 = (ss >= 2.0f), c4 = (ss >= 4.0f);
                float kf = c2 ? (c4 ? 2.0f   : 1.0f ) : 0.0f;
                float fs = c2 ? (c4 ? 0.25f  : 0.5f ) : 1.0f;

                // d' = L2E*|x-y|^2 via packed f32x2 FMAs
                u64 acc2 = pk2(sqx[s], yq[(u - s) & 3]);
                #pragma unroll
                for (int kp = 0; kp < 4; ++kp)
                    acc2 = fma2(xs2[s][kp], yp2[(u - s) & 3][kp], acc2);
                float lo, hi; upk2(lo, hi, acc2);

                float gn = (lo + hi) + (m - kf);
                g[wIdx][s] = vd[u - s + 3] ? gn : BIGV;
                e[wIdx][s] = ss * fs;
            }

            // harvest: pair A at p=254 (p0=252,u=2), pair B at p=382 (p0=380,u=2)
            if (u == 2 && lane == 31) {
                if (p0 == 252) out[outA]     = (g[0][3] - lg2f_(e[0][3])) * LN2;
                if (p0 == 380) out[outA + 1] = (g[0][3] - lg2f_(e[0][3])) * LN2;
            }

            shPg = sh1g;
            shPe = sh1e;
        }
    }
}

extern "C" void kernel_launch(void* const* d_in, const int* in_sizes, int n_in,
                              void* d_out, int out_size)
{
    const float* X = (const float*)d_in[0];
    const float* Y = (const float*)d_in[1];
    if (n_in >= 2 && in_sizes[0] < in_sizes[1]) {
        const float* t = X; X = Y; Y = t;
    }
    float* out = (float*)d_out;

    sdtw_kernel<<<256, 128>>>(X, Y, out);
}

// round 5
// speedup vs baseline: 1.1885x; 1.1085x over previous
#include <cuda_runtime.h>

#define BIGV 10000000000.0f
#define L2E  1.4426950408889634f
#define LN2  0.6931471805599453f

typedef unsigned long long u64;

__device__ __forceinline__ float ex2f_(float x){ float r; asm("ex2.approx.f32 %0, %1;" : "=f"(r) : "f"(x)); return r; }
__device__ __forceinline__ float lg2f_(float x){ float r; asm("lg2.approx.f32 %0, %1;" : "=f"(r) : "f"(x)); return r; }
__device__ __forceinline__ float i2f_(unsigned x){ float r; asm("cvt.rn.f32.u32 %0, %1;" : "=f"(r) : "r"(x)); return r; }
__device__ __forceinline__ u64 pk2(float lo, float hi){ u64 r; asm("mov.b64 %0,{%1,%2};" : "=l"(r) : "f"(lo), "f"(hi)); return r; }
__device__ __forceinline__ void upk2(float& lo, float& hi, u64 v){ asm("mov.b64 {%0,%1},%2;" : "=f"(lo), "=f"(hi) : "l"(v)); }
__device__ __forceinline__ u64 fma2(u64 a, u64 b, u64 c){ u64 r; asm("fma.rn.f32x2 %0,%1,%2,%3;" : "=l"(r) : "l"(a), "l"(b), "l"(c)); return r; }

// One warp = two (a,b) pairs fused in anti-phase (128-step offset), 4 rows/thread.
// DP carried as V = g - lg2(e), e in [1,2): no lg2 in the loop; renorm is an exact
// float-exponent bit split. Dead cells are unmasked (their garbage provably never
// reaches a valid cell: validity depends only on column index, and dead columns
// are read only by dead columns).
__global__ __launch_bounds__(128)
void sdtw_kernel(const float* __restrict__ X, const float* __restrict__ Y,
                 float* __restrict__ out)
{
    // per tile: y rows as k-pairs  sy[t*1152 + (j&3)*256 + (k>>1)*64 + (j>>2)*2 + (k&1)]
    //           sqy (L2E-scaled)   sy[t*1152 + 1024 + (j&3)*32 + (j>>2)]
    __shared__ __align__(8) float sy[2 * 1152];

    const int tid  = threadIdx.x;
    const int lane = tid & 31;
    const int wid  = tid >> 5;

    const int b0 = (blockIdx.x & 7) * 2;
    const int a  = (blockIdx.x >> 3) * 4 + wid;

    for (int rep = 0; rep < 2; ++rep) {
        int gr   = tid + rep * 128;
        int tile = gr >> 7;
        int j    = gr & 127;
        const float* yrow = Y + (size_t)(b0 + tile) * 1024 + j * 8;
        float sq = 0.f;
        int base = tile * 1152 + (j & 3) * 256 + (j >> 2) * 2;
        #pragma unroll
        for (int k = 0; k < 8; ++k) {
            float vv = yrow[k];
            sq = fmaf(vv, vv, sq);
            sy[base + (k >> 1) * 64 + (k & 1)] = vv;
        }
        sy[tile * 1152 + 1024 + (j & 3) * 32 + (j >> 2)] = sq * L2E;
    }

    // X: packed xs2 = -2*L2E*x ; sqx = L2E*|x|^2 + 127 (bias cancels the
    // raw exponent field from the renorm: true k = kff - 127)
    u64   xs2[4][4];
    float sqx[4];
    {
        const float* xp = X + (size_t)a * 1024 + lane * 32;
        #pragma unroll
        for (int s = 0; s < 4; ++s) {
            float acc = 0.f;
            #pragma unroll
            for (int kp = 0; kp < 4; ++kp) {
                float f0 = xp[s * 8 + 2 * kp];
                float f1 = xp[s * 8 + 2 * kp + 1];
                acc = fmaf(f0, f0, fmaf(f1, f1, acc));
                xs2[s][kp] = pk2(f0 * (-2.0f * L2E), f1 * (-2.0f * L2E));
            }
            sqx[s] = fmaf(acc, L2E, 127.0f);
        }
    }
    __syncthreads();

    float g[2][4], e[2][4];
    #pragma unroll
    for (int s = 0; s < 4; ++s) {
        g[0][s] = BIGV; g[1][s] = BIGV;
        e[0][s] = 1.0f; e[1][s] = 1.0f;
    }

    // Y register pipeline: buffer (p)&3 holds row ja0(p) = p - 4*lane.
    // Buffer (p+1)&3 is refilled at the END of step p (after slot 3, its last
    // reader at step p, has consumed it) -> ~full-step LDS latency cover.
    u64   yp2[4][4];
    float yq[4];
    #pragma unroll
    for (int q = 0; q < 4; ++q) {
        yq[q] = 0.f;
        #pragma unroll
        for (int kp = 0; kp < 4; ++kp) yp2[q][kp] = 0ull;
    }

    const int lane4 = lane * 4;

    // prologue: buffer 0 <- row ja0(p=0) = -lane4 (wrapped; real only for lane 0)
    {
        unsigned jb = (unsigned)(-lane4) & 255u;
        int t    = (int)(jb >> 7) * 1152;
        int off  = (int)((jb >> 2) & 31u);
        #pragma unroll
        for (int kp = 0; kp < 4; ++kp)
            yp2[0][kp] = *reinterpret_cast<const u64*>(&sy[t + off * 2 + kp * 64]);
        yq[0] = sy[t + 1024 + off];
    }

    float shPg = BIGV, shPe = 1.0f;
    const int outA = a * 16 + b0;

    for (int p0 = 0; p0 < 384; p0 += 4) {
        const int j0      = p0 - lane4;
        const unsigned jc = (unsigned)j0 & 255u;
        const unsigned jn = (unsigned)(j0 + 4) & 255u;
        const int base0   = (int)((jc >> 7) * 1152u + ((jc >> 2) & 31u) * 2u);
        const int qb0     = (int)((jc >> 7) * 1152u + 1024u + ((jc >> 2) & 31u));
        const int base1   = (int)((jn >> 7) * 1152u + ((jn >> 2) & 31u) * 2u);
        const int qb1     = (int)((jn >> 7) * 1152u + 1024u + ((jn >> 2) & 31u));
        const bool bj0    = ((jc & 127u) == 0u);   // j==0 boundary fires only at cells s==u

        #pragma unroll
        for (int u = 0; u < 4; ++u) {
            const int wIdx = u & 1;
            const int rIdx = wIdx ^ 1;

            const float sh1g = __shfl_up_sync(0xffffffffu, g[rIdx][3], 1);
            const float sh1e = __shfl_up_sync(0xffffffffu, e[rIdx][3], 1);

            // reverse slot order: slot s reads g[wIdx][s-1] (prev2) before slot s-1 writes it
            #pragma unroll
            for (int s = 3; s >= 0; --s) {
                float gu, gl, gd, eu, el, ed;
                if (s == 0) {
                    gu = (lane == 0) ? BIGV : sh1g;  eu = sh1e;
                    if (u == 0) {
                        gl = bj0 ? BIGV : g[rIdx][0];  el = e[rIdx][0];
                        if (lane == 0) { gd = bj0 ? 0.0f : BIGV;  ed = 1.0f; }
                        else           { gd = bj0 ? BIGV : shPg;  ed = shPe; }
                    } else {
                        gl = g[rIdx][0];                el = e[rIdx][0];
                        gd = (lane == 0) ? BIGV : shPg; ed = shPe;
                    }
                } else {
                    gu = g[rIdx][s - 1];  eu = e[rIdx][s - 1];
                    if (s == u) {
                        gl = bj0 ? BIGV : g[rIdx][s];      el = e[rIdx][s];
                        gd = bj0 ? BIGV : g[wIdx][s - 1];  ed = e[wIdx][s - 1];
                    } else {
                        gl = g[rIdx][s];      el = e[rIdx][s];
                        gd = g[wIdx][s - 1];  ed = e[wIdx][s - 1];
                    }
                }

                // exp-split softmin: shift by exact min of g; one term is exactly e_i >= 1
                float m  = fminf(fminf(gu, gl), gd);
                float ss = fmaf(eu, ex2f_(m - gu),
                           fmaf(el, ex2f_(m - gl), ed * ex2f_(m - gd)));  // ss >= 1

                // exact renorm via float exponent bits
                unsigned ub = __float_as_uint(ss);
                float kff   = i2f_(ub >> 23);                                    // k + 127
                float en    = __uint_as_float((ub & 0x007FFFFFu) | 0x3F800000u); // in [1,2)

                // d' + 127 via packed FMAs (sqx carries the +127 bias)
                u64 acc2 = pk2(sqx[s], yq[(u - s) & 3]);
                #pragma unroll
                for (int kp = 0; kp < 4; ++kp)
                    acc2 = fma2(xs2[s][kp], yp2[(u - s) & 3][kp], acc2);
                float lo, hi; upk2(lo, hi, acc2);

                g[wIdx][s] = (lo + hi) + (m - kff);
                e[wIdx][s] = en;
            }

            // refill buffer (u+1)&3 with row j0+u+1 AFTER its last reader (slot 3) is done
            {
                const int pb = (u < 3) ? (base0 + (u + 1) * 256) : base1;
                #pragma unroll
                for (int kp = 0; kp < 4; ++kp)
                    yp2[(u + 1) & 3][kp] = *reinterpret_cast<const u64*>(&sy[pb + kp * 64]);
                yq[(u + 1) & 3] = (u < 3) ? sy[qb0 + (u + 1) * 32] : sy[qb1];
            }

            // harvest: pair A at p=254 (p0=252,u=2), pair B at p=382 (p0=380,u=2)
            if (u == 2 && lane == 31) {
                if (p0 == 252) out[outA]     = (g[0][3] - lg2f_(e[0][3])) * LN2;
                if (p0 == 380) out[outA + 1] = (g[0][3] - lg2f_(e[0][3])) * LN2;
            }

            shPg = sh1g;
            shPe = sh1e;
        }
    }
}

extern "C" void kernel_launch(void* const* d_in, const int* in_sizes, int n_in,
                              void* d_out, int out_size)
{
    const float* X = (const float*)d_in[0];
    const float* Y = (const float*)d_in[1];
    if (n_in >= 2 && in_sizes[0] < in_sizes[1]) {
        const float* t = X; X = Y; Y = t;
    }
    float* out = (float*)d_out;

    sdtw_kernel<<<256, 128>>>(X, Y, out);
}